// round 11
// baseline (speedup 1.0000x reference)
#include <cuda_runtime.h>
#include <cuda_bf16.h>

#define Bn 8
#define Sn 512
#define Kn 16
#define Rr 8            // output rows per block (2 halves of 4 per thread)
#define SW2 518         // padded shared row width: idx = col+1, zeros at idx 0 and 513
#define EMPTY_DIST 362.1f
#define FAR_COORD 1.0e18f

// Persistent scratch (no allocations allowed). Starts zeroed (.bss);
// the last main block resets counters after use -> deterministic replays.
__device__ float    g_py[Bn][Kn];
__device__ float    g_px[Bn][Kn];
__device__ int      g_cnt[Bn];
__device__ unsigned g_maxbits[Bn];
__device__ double   g_numer[Bn];
__device__ double   g_gradsum;
__device__ unsigned g_done;

// ---------------------------------------------------------------------------
// Kernel 1: collect nonzero label pixels. Wide grid: (slices, Bn).
// ---------------------------------------------------------------------------
#define CSLICES 64
__global__ __launch_bounds__(256) void collect_kernel(const float* __restrict__ pt) {
    const int b = blockIdx.y;
    const int slice = blockIdx.x;
    const int n4_per_slice = (Sn * Sn / 4) / CSLICES;      // 1024 float4
    const float4* p = (const float4*)(pt + (size_t)b * Sn * Sn) + slice * n4_per_slice;
    for (int i = threadIdx.x; i < n4_per_slice; i += 256) {
        float4 v = p[i];
        if (v.x != 0.f || v.y != 0.f || v.z != 0.f || v.w != 0.f) {
            float vv[4] = {v.x, v.y, v.z, v.w};
            int base_idx = (slice * n4_per_slice + i) * 4;
            #pragma unroll
            for (int j = 0; j < 4; j++) {
                if (vv[j] != 0.f) {
                    int idx = base_idx + j;
                    int slot = atomicAdd(&g_cnt[b], 1);
                    if (slot < Kn) {
                        g_py[b][slot] = (float)(idx / Sn);
                        g_px[b][slot] = (float)(idx % Sn);
                    }
                }
            }
        }
    }
}

// ---------------------------------------------------------------------------
// Kernel 2: fused distance + sobel + reductions + finalize.
// grid (Sn/Rr, Bn), 512 threads, 3 blocks/SM. Each thread: 2 cols x 4 rows.
// Thread x: cx = x&255 -> cols (2cx, 2cx+1); ty = x>>8 -> rows y0+4ty..+3.
// ---------------------------------------------------------------------------
__global__ __launch_bounds__(512, 3) void main_kernel(const float* __restrict__ pred,
                                                      const float* __restrict__ ori,
                                                      float* __restrict__ out) {
    __shared__ float s_img[Rr + 2][SW2];    // idx = col+1; idx 0 and 513 are zero
    __shared__ float sh_s[16], sh_g[16], sh_m[16];

    const int y0 = blockIdx.x * Rr;
    const int b  = blockIdx.y;
    const int x  = threadIdx.x;
    const int lane = x & 31;
    const int cx = x & 255;
    const int ty = x >> 8;
    const int c0 = cx * 2;

    const float* __restrict__ pb = pred + b * (Sn * Sn);
    const float* __restrict__ ob = ori  + b * (Sn * Sn);

    // point coords in registers (lane<16), broadcast later via shfl. L2-hot.
    int cload = 0;
    float pxv = FAR_COORD, pyv = FAR_COORD;
    if (lane == 0) cload = g_cnt[b];
    const int cnt = min(__shfl_sync(0xffffffffu, cload, 0), Kn);
    if (lane < Kn) {
        if (lane < cnt) { pxv = g_px[b][lane]; pyv = g_py[b][lane]; }
    }

    if (x < 2) {
        int col = (x == 0) ? 0 : 513;
        #pragma unroll
        for (int rr = 0; rr < Rr + 2; rr++) s_img[rr][col] = 0.f;
    }

    // --- phase 1: float2 global loads; thread ty loads smem rows 5ty..5ty+4 ---
    float pvA[4], pvB[4];
    #pragma unroll
    for (int i = 0; i < 5; i++) {
        const int sr = ty * 5 + i;          // smem row
        const int yy = y0 - 1 + sr;         // global row
        float2 p2 = make_float2(0.f, 0.f), v2 = make_float2(0.f, 0.f);
        if (yy >= 0 && yy < Sn) {
            const int o = yy * Sn + c0;
            p2 = *(const float2*)(pb + o);
            float2 o2 = *(const float2*)(ob + o);
            v2.x = p2.x * o2.x;
            v2.y = p2.y * o2.y;
        }
        s_img[sr][c0 + 1] = v2.x;
        s_img[sr][c0 + 2] = v2.y;
        const int pr = i - 1 + ty;          // output-row index for pred
        if (pr >= 0 && pr < 4) { pvA[pr] = p2.x; pvB[pr] = p2.y; }
    }

    const float fx0 = (float)c0;
    const float fyt = (float)(y0 + 4 * ty);

    // --- phase 2a: exact per-warp culling over the warp's 64x4 tile ---
    unsigned keep;
    {
        const float x0f = (float)(2 * (cx & ~31));
        const float x1f = x0f + 63.0f;
        const float y1f = fyt + 3.0f;
        float lb = 3.0e38f, ubi = 3.0e38f;
        if (lane < Kn) {
            float dxl = x0f - pxv, dxr = pxv - x1f;
            float dxm = fmaxf(0.f, fmaxf(dxl, dxr));
            float dxM = fmaxf(fabsf(dxl), fabsf(x1f - pxv));
            float dyl = fyt - pyv, dyr = pyv - y1f;
            float dym = fmaxf(0.f, fmaxf(dyl, dyr));
            float dyM = fmaxf(fabsf(dyl), fabsf(y1f - pyv));
            lb  = fmaf(dxm, dxm, dym * dym);
            ubi = fmaf(dxM, dxM, dyM * dyM);
        }
        float ub = ubi;
        #pragma unroll
        for (int o = 16; o > 0; o >>= 1)
            ub = fminf(ub, __shfl_xor_sync(0xffffffffu, ub, o));
        keep = __ballot_sync(0xffffffffu, lb <= ub);
    }

    // --- phase 2b: distance mins (exact ints). colB: (dx+1)^2 = dx^2+2dx+1 ---
    float mA[4], mB[4];
    #pragma unroll
    for (int r = 0; r < 4; r++) { mA[r] = 3.0e38f; mB[r] = 3.0e38f; }

    unsigned mask = keep;
    while (mask) {
        int i = __ffs(mask) - 1;
        mask &= mask - 1;
        float px_i = __shfl_sync(0xffffffffu, pxv, i);
        float py_i = __shfl_sync(0xffffffffu, pyv, i);
        float dxv = fx0 - px_i;
        float dy0 = fyt - py_i;
        float cA = fmaf(dy0, dy0, dxv * dxv);
        float cB = cA + fmaf(2.0f, dxv, 1.0f);
        float e  = dy0 + dy0;
        #pragma unroll
        for (int r = 0; r < 4; r++) {
            float re = fmaf((float)r, e, 0.f);
            mA[r] = fminf(mA[r], cA + re);
            mB[r] = fminf(mB[r], cB + re);
        }
    }

    float vsum = 0.f, vmax = 0.f;
    #pragma unroll
    for (int r = 0; r < 4; r++) {
        float r2 = (float)(r * r);
        float dA = (cnt > 0) ? sqrtf(mA[r] + r2) : EMPTY_DIST;
        float dB = (cnt > 0) ? sqrtf(mB[r] + r2) : EMPTY_DIST;
        float ddA = (dA > 1.0f) ? (dA - 1.0f) : 0.f;
        float ddB = (dB > 1.0f) ? (dB - 1.0f) : 0.f;
        vsum += pvA[r] * ddA + pvB[r] * ddB;
        vmax = fmaxf(vmax, fmaxf(ddA, ddB));
    }

    __syncthreads();

    // --- phase 3: sobel, 2 pixels/row via LDS.64 pairs, rolling 4-wide window ---
    float gsum = 0.f;
    const bool okA = (c0 >= 1);             // col 0 is the only invalid A col
    const bool okB = (c0 + 1 <= Sn - 2);    // col 511 is the only invalid B col

    // window idx c0..c0+3 = cols c0-1..c0+2 (8B aligned: c0 even, row stride 2072B)
    float2 w0a = *(const float2*)&s_img[4 * ty][c0];
    float2 w0b = *(const float2*)&s_img[4 * ty][c0 + 2];
    float2 w1a = *(const float2*)&s_img[4 * ty + 1][c0];
    float2 w1b = *(const float2*)&s_img[4 * ty + 1][c0 + 2];

    #pragma unroll
    for (int r = 0; r < 4; r++) {
        const int y = y0 + 4 * ty + r;
        float2 w2a = *(const float2*)&s_img[4 * ty + 2 + r][c0];
        float2 w2b = *(const float2*)&s_img[4 * ty + 2 + r][c0 + 2];

        if (y >= 1 && y <= Sn - 2) {
            if (okA) {
                float t = w0a.y - w2a.y;            // n01-n21
                float u = w1b.x - w1a.x;            // n12-n10
                float p = w0b.x - w2a.x;            // n02-n20
                float q = w0a.x - w2b.x;            // n00-n22
                float g0 = fmaf(2.f, u, p - q);
                float g1 = fmaf(2.f, t, p + q);
                float g2 = fmaf(2.f, q, t - u);
                float g3 = fmaf(2.f, p, t + u);
                gsum += fmaxf(fmaxf(fabsf(g0), fabsf(g1)), fmaxf(fabsf(g2), fabsf(g3)));
            }
            if (okB) {
                float t = w0b.x - w2b.x;
                float u = w1b.y - w1a.y;
                float p = w0b.y - w2a.y;
                float q = w0a.y - w2b.y;
                float g0 = fmaf(2.f, u, p - q);
                float g1 = fmaf(2.f, t, p + q);
                float g2 = fmaf(2.f, q, t - u);
                float g3 = fmaf(2.f, p, t + u);
                gsum += fmaxf(fmaxf(fabsf(g0), fabsf(g1)), fmaxf(fabsf(g2), fabsf(g3)));
            }
        }

        w0a = w1a; w0b = w1b;
        w1a = w2a; w1b = w2b;
    }

    // --- block reduction: sum(vsum), sum(gsum), max(vmax) ---
    #pragma unroll
    for (int o = 16; o > 0; o >>= 1) {
        vsum += __shfl_down_sync(0xffffffffu, vsum, o);
        gsum += __shfl_down_sync(0xffffffffu, gsum, o);
        vmax = fmaxf(vmax, __shfl_down_sync(0xffffffffu, vmax, o));
    }
    const int wid = x >> 5;
    if (lane == 0) { sh_s[wid] = vsum; sh_g[wid] = gsum; sh_m[wid] = vmax; }
    __syncthreads();
    if (wid == 0) {
        vsum = (lane < 16) ? sh_s[lane] : 0.f;
        gsum = (lane < 16) ? sh_g[lane] : 0.f;
        vmax = (lane < 16) ? sh_m[lane] : 0.f;
        #pragma unroll
        for (int o = 8; o > 0; o >>= 1) {
            vsum += __shfl_down_sync(0xffffffffu, vsum, o);
            gsum += __shfl_down_sync(0xffffffffu, gsum, o);
            vmax = fmaxf(vmax, __shfl_down_sync(0xffffffffu, vmax, o));
        }
        if (lane == 0) {
            atomicAdd(&g_numer[b], (double)vsum);
            atomicAdd(&g_gradsum, (double)gsum);
            atomicMax(&g_maxbits[b], __float_as_uint(vmax));

            __threadfence();
            unsigned ticket = atomicAdd(&g_done, 1u);
            const unsigned total = (Sn / Rr) * Bn;
            if (ticket == total - 1u) {
                double acc = 0.0;
                #pragma unroll
                for (int bb = 0; bb < Bn; bb++) {
                    float mx = __uint_as_float(g_maxbits[bb]);
                    acc += g_numer[bb] / (double)mx;
                    g_numer[bb] = 0.0;
                    g_maxbits[bb] = 0u;
                    g_cnt[bb] = 0;
                }
                const double denom = (double)Sn * (double)Sn * (double)Bn;
                out[0] = (float)(acc / denom);
                out[1] = (float)(g_gradsum / denom);
                g_gradsum = 0.0;
                g_done = 0u;
                __threadfence();
            }
        }
    }
}

extern "C" void kernel_launch(void* const* d_in, const int* in_sizes, int n_in,
                              void* d_out, int out_size) {
    const float* pred = (const float*)d_in[0];
    const float* ptl  = (const float*)d_in[1];
    const float* ori  = (const float*)d_in[2];
    float* out = (float*)d_out;

    collect_kernel<<<dim3(CSLICES, Bn), 256>>>(ptl);
    main_kernel<<<dim3(Sn / Rr, Bn), 512>>>(pred, ori, out);
}

// round 12
// speedup vs baseline: 1.0917x; 1.0917x over previous
#include <cuda_runtime.h>
#include <cuda_bf16.h>

#define Bn 8
#define Sn 512
#define Kn 16
#define Rr 8            // output rows per block
#define SW (Sn + 4)     // padded shared row width (cols 0 and Sn+1 are zero)
#define EMPTY_DIST 362.1f
#define FAR_COORD 1.0e18f

// Persistent scratch (no allocations allowed). Starts zeroed (.bss);
// the last main block resets counters after use -> deterministic replays.
__device__ float    g_py[Bn][Kn];
__device__ float    g_px[Bn][Kn];
__device__ int      g_cnt[Bn];
__device__ unsigned g_maxbits[Bn];
__device__ double   g_numer[Bn];
__device__ double   g_gradsum;
__device__ unsigned g_done;

// ---------------------------------------------------------------------------
// Kernel 1: collect nonzero label pixels. Wide grid: (slices, Bn).
// ---------------------------------------------------------------------------
#define CSLICES 64
__global__ __launch_bounds__(256) void collect_kernel(const float* __restrict__ pt) {
    const int b = blockIdx.y;
    const int slice = blockIdx.x;
    const int n4_per_slice = (Sn * Sn / 4) / CSLICES;      // 1024 float4
    const float4* p = (const float4*)(pt + (size_t)b * Sn * Sn) + slice * n4_per_slice;
    for (int i = threadIdx.x; i < n4_per_slice; i += 256) {
        float4 v = p[i];
        if (v.x != 0.f || v.y != 0.f || v.z != 0.f || v.w != 0.f) {
            float vv[4] = {v.x, v.y, v.z, v.w};
            int base_idx = (slice * n4_per_slice + i) * 4;
            #pragma unroll
            for (int j = 0; j < 4; j++) {
                if (vv[j] != 0.f) {
                    int idx = base_idx + j;
                    int slot = atomicAdd(&g_cnt[b], 1);
                    if (slot < Kn) {
                        g_py[b][slot] = (float)(idx / Sn);
                        g_px[b][slot] = (float)(idx % Sn);
                    }
                }
            }
        }
    }
}

// ---------------------------------------------------------------------------
// Kernel 2: fused distance + sobel + reductions + finalize.
// grid (Sn/Rr, Bn), 512 threads, 3 blocks/SM. Branch-free inner loops:
// halo rows peeled (uniform branches), sobel masked with FSEL/FFMA not BSSY.
// ---------------------------------------------------------------------------
__global__ __launch_bounds__(Sn, 3) void main_kernel(const float* __restrict__ pred,
                                                     const float* __restrict__ ori,
                                                     float* __restrict__ out) {
    __shared__ float s_img[Rr + 2][SW];     // cols 0 and Sn+1 are zero
    __shared__ float sh_s[16], sh_g[16], sh_m[16];

    const int y0 = blockIdx.x * Rr;
    const int b  = blockIdx.y;
    const int x  = threadIdx.x;
    const int lane = x & 31;

    const float* __restrict__ pb = pred + b * (Sn * Sn);
    const float* __restrict__ ob = ori  + b * (Sn * Sn);

    // point coords in registers (lane<16), broadcast later via shfl. L2-hot.
    int cload = 0;
    float pxv = FAR_COORD, pyv = FAR_COORD;
    if (lane == 0) cload = g_cnt[b];
    const int cnt = min(__shfl_sync(0xffffffffu, cload, 0), Kn);
    if (lane < Kn) {
        if (lane < cnt) { pxv = g_px[b][lane]; pyv = g_py[b][lane]; }
    }

    if (x < 2) {
        int col = (x == 0) ? 0 : (Sn + 1);
        #pragma unroll
        for (int rr = 0; rr < Rr + 2; rr++) s_img[rr][col] = 0.f;
    }

    // --- phase 1: global loads + smem stores. Interior rows branch-free;
    //     halo rows peeled (block-uniform branches). ---
    float pv[Rr];
    {   // top halo: yy = y0-1, invalid only for blockIdx.x == 0
        float v = 0.f;
        if (y0 > 0) {
            int o = (y0 - 1) * Sn + x;
            v = __ldg(pb + o) * __ldg(ob + o);
        }
        s_img[0][x + 1] = v;
    }
    #pragma unroll
    for (int rr = 1; rr <= Rr; rr++) {      // yy = y0+rr-1 in [0,511] always
        int o = (y0 + rr - 1) * Sn + x;
        float pval = __ldg(pb + o);
        pv[rr - 1] = pval;
        s_img[rr][x + 1] = pval * __ldg(ob + o);
    }
    {   // bottom halo: yy = y0+Rr, invalid only for last block
        float v = 0.f;
        if (y0 + Rr < Sn) {
            int o = (y0 + Rr) * Sn + x;
            v = __ldg(pb + o) * __ldg(ob + o);
        }
        s_img[Rr + 1][x + 1] = v;
    }

    const float fx  = (float)x;
    const float fy0 = (float)y0;

    // --- phase 2a: exact per-warp point culling over the warp's 32xRr tile ---
    unsigned keep;
    {
        const float x0f = (float)(x & ~31);
        const float x1f = x0f + 31.0f;
        const float y1f = fy0 + (float)(Rr - 1);
        float lb = 3.0e38f, ubi = 3.0e38f;
        if (lane < Kn) {
            float dxl = x0f - pxv, dxr = pxv - x1f;
            float dxm = fmaxf(0.f, fmaxf(dxl, dxr));
            float dxM = fmaxf(fabsf(dxl), fabsf(x1f - pxv));
            float dyl = fy0 - pyv, dyr = pyv - y1f;
            float dym = fmaxf(0.f, fmaxf(dyl, dyr));
            float dyM = fmaxf(fabsf(dyl), fabsf(y1f - pyv));
            lb  = fmaf(dxm, dxm, dym * dym);
            ubi = fmaf(dxM, dxM, dyM * dyM);
        }
        float ub = ubi;
        #pragma unroll
        for (int o = 16; o > 0; o >>= 1)
            ub = fminf(ub, __shfl_xor_sync(0xffffffffu, ub, o));
        keep = __ballot_sync(0xffffffffu, lb <= ub);
    }

    // --- phase 2b: distance mins over surviving points (shfl-broadcast) ---
    float m[Rr];
    #pragma unroll
    for (int r = 0; r < Rr; r++) m[r] = 3.0e38f;

    unsigned mask = keep;
    while (mask) {
        int i = __ffs(mask) - 1;
        mask &= mask - 1;
        float px_i = __shfl_sync(0xffffffffu, pxv, i);
        float py_i = __shfl_sync(0xffffffffu, pyv, i);
        float dxv = fx - px_i;
        float dy0 = fy0 - py_i;
        float c = fmaf(dy0, dy0, dxv * dxv);
        float e = dy0 + dy0;
        #pragma unroll
        for (int r = 0; r < Rr; r++)
            m[r] = fminf(m[r], fmaf((float)r, e, c));       // d2(r) = m + r^2 later
    }

    float vsum = 0.f, vmax = 0.f;
    #pragma unroll
    for (int r = 0; r < Rr; r++) {
        float d2 = m[r] + (float)(r * r);
        float dist = (cnt > 0) ? sqrtf(d2) : EMPTY_DIST;
        float dd = fmaxf(dist - 1.0f, 0.f);                 // branch-free threshold
        vsum += pv[r] * dd;
        vmax = fmaxf(vmax, dd);
    }

    __syncthreads();

    // --- phase 3: branch-free rolling-window sobel (masked accumulate) ---
    float gsum = 0.f;
    const float xokf = (x >= 1 && x <= Sn - 2) ? 1.f : 0.f;

    float a0l = s_img[0][x], a0c = s_img[0][x + 1], a0r = s_img[0][x + 2];
    float a1l = s_img[1][x],                        a1r = s_img[1][x + 2];

    #pragma unroll
    for (int r = 0; r < Rr; r++) {
        const int y = y0 + r;
        float a2l = s_img[r + 2][x], a2c = s_img[r + 2][x + 1], a2r = s_img[r + 2][x + 2];

        float t = a0c - a2c;     // n01 - n21
        float u = a1r - a1l;     // n12 - n10
        float p = a0r - a2l;     // n02 - n20
        float q = a0l - a2r;     // n00 - n22
        float g0 = fmaf(2.f, u, p - q);
        float g1 = fmaf(2.f, t, p + q);
        float g2 = fmaf(2.f, q, t - u);
        float g3 = fmaf(2.f, p, t + u);
        float gm = fmaxf(fmaxf(fabsf(g0), fabsf(g1)), fmaxf(fabsf(g2), fabsf(g3)));
        float maskf = (y >= 1 && y <= Sn - 2) ? xokf : 0.f;  // y part block-uniform
        gsum = fmaf(maskf, gm, gsum);

        a0l = a1l; a0c = s_img[r + 1][x + 1]; a0r = a1r;
        a1l = a2l;                            a1r = a2r;
    }

    // --- block reduction: sum(vsum), sum(gsum), max(vmax) ---
    #pragma unroll
    for (int o = 16; o > 0; o >>= 1) {
        vsum += __shfl_down_sync(0xffffffffu, vsum, o);
        gsum += __shfl_down_sync(0xffffffffu, gsum, o);
        vmax = fmaxf(vmax, __shfl_down_sync(0xffffffffu, vmax, o));
    }
    const int wid = x >> 5;
    if (lane == 0) { sh_s[wid] = vsum; sh_g[wid] = gsum; sh_m[wid] = vmax; }
    __syncthreads();
    if (wid == 0) {
        vsum = (lane < 16) ? sh_s[lane] : 0.f;
        gsum = (lane < 16) ? sh_g[lane] : 0.f;
        vmax = (lane < 16) ? sh_m[lane] : 0.f;
        #pragma unroll
        for (int o = 8; o > 0; o >>= 1) {
            vsum += __shfl_down_sync(0xffffffffu, vsum, o);
            gsum += __shfl_down_sync(0xffffffffu, gsum, o);
            vmax = fmaxf(vmax, __shfl_down_sync(0xffffffffu, vmax, o));
        }
        if (lane == 0) {
            atomicAdd(&g_numer[b], (double)vsum);
            atomicAdd(&g_gradsum, (double)gsum);
            atomicMax(&g_maxbits[b], __float_as_uint(vmax));

            __threadfence();
            unsigned ticket = atomicAdd(&g_done, 1u);
            const unsigned total = (Sn / Rr) * Bn;
            if (ticket == total - 1u) {
                double acc = 0.0;
                #pragma unroll
                for (int bb = 0; bb < Bn; bb++) {
                    float mx = __uint_as_float(g_maxbits[bb]);
                    acc += g_numer[bb] / (double)mx;
                    g_numer[bb] = 0.0;
                    g_maxbits[bb] = 0u;
                    g_cnt[bb] = 0;
                }
                const double denom = (double)Sn * (double)Sn * (double)Bn;
                out[0] = (float)(acc / denom);
                out[1] = (float)(g_gradsum / denom);
                g_gradsum = 0.0;
                g_done = 0u;
                __threadfence();
            }
        }
    }
}

extern "C" void kernel_launch(void* const* d_in, const int* in_sizes, int n_in,
                              void* d_out, int out_size) {
    const float* pred = (const float*)d_in[0];
    const float* ptl  = (const float*)d_in[1];
    const float* ori  = (const float*)d_in[2];
    float* out = (float*)d_out;

    collect_kernel<<<dim3(CSLICES, Bn), 256>>>(ptl);
    main_kernel<<<dim3(Sn / Rr, Bn), Sn>>>(pred, ori, out);
}

// round 13
// speedup vs baseline: 1.1064x; 1.0135x over previous
#include <cuda_runtime.h>
#include <cuda_bf16.h>

#define Bn 8
#define Sn 512
#define Kn 16
#define Rr 8            // output rows per block
#define SW (Sn + 4)     // padded shared row width (cols 0 and Sn+1 are zero)
#define TILES (Sn / Rr) // 64 blocks per batch
#define EMPTY_DIST 362.1f
#define FAR_COORD 1.0e18f

// Persistent scratch (no allocations allowed). Starts zeroed (.bss);
// the last block resets everything after use -> deterministic replays.
__device__ float    g_py[Bn][Kn];
__device__ float    g_px[Bn][Kn];
__device__ int      g_cnt[Bn];
__device__ int      g_scan_done[Bn];   // blocks of batch b that finished scanning
__device__ unsigned g_maxbits[Bn];
__device__ double   g_numer[Bn];
__device__ double   g_gradsum;
__device__ unsigned g_done;

// ---------------------------------------------------------------------------
// Single fused kernel: label scan + distance + sobel + reductions + finalize.
// grid (TILES, Bn), 512 threads, 4 blocks/SM, launched COOPERATIVELY so the
// whole grid is co-resident -> per-batch spin barrier cannot deadlock.
// ---------------------------------------------------------------------------
__global__ __launch_bounds__(512, 4) void fused_kernel(const float* __restrict__ pred,
                                                       const float* __restrict__ ori,
                                                       const float* __restrict__ ptl,
                                                       float* __restrict__ out) {
    __shared__ float s_img[Rr + 2][SW];     // cols 0 and Sn+1 are zero
    __shared__ float s_pred[Rr][Sn];        // own-column pred values (reg relief)
    __shared__ float sh_s[16], sh_g[16], sh_m[16];

    const int y0 = blockIdx.x * Rr;
    const int b  = blockIdx.y;
    const int x  = threadIdx.x;
    const int lane = x & 31;

    const float* __restrict__ pb = pred + b * (Sn * Sn);
    const float* __restrict__ ob = ori  + b * (Sn * Sn);

    // --- phase 0: scan this block's own row-slice of pt_label for points ---
    {
        const float4* ps = (const float4*)(ptl + b * (Sn * Sn) + y0 * Sn);
        #pragma unroll
        for (int i = 0; i < (Rr * Sn / 4) / 512; i++) {     // 2 float4 per thread
            int idx4 = x + i * 512;
            float4 v = ps[idx4];
            if (v.x != 0.f || v.y != 0.f || v.z != 0.f || v.w != 0.f) {
                float vv[4] = {v.x, v.y, v.z, v.w};
                #pragma unroll
                for (int j = 0; j < 4; j++) {
                    if (vv[j] != 0.f) {
                        int idx = y0 * Sn + idx4 * 4 + j;
                        int slot = atomicAdd(&g_cnt[b], 1);
                        if (slot < Kn) {
                            g_py[b][slot] = (float)(idx >> 9);
                            g_px[b][slot] = (float)(idx & (Sn - 1));
                        }
                    }
                }
            }
        }
    }
    __syncthreads();                 // all scan writes of this block done
    if (x == 0) {
        __threadfence();             // release g_px/g_py/g_cnt writes
        atomicAdd(&g_scan_done[b], 1);
    }

    if (x < 2) {
        int col = (x == 0) ? 0 : (Sn + 1);
        #pragma unroll
        for (int rr = 0; rr < Rr + 2; rr++) s_img[rr][col] = 0.f;
    }

    // --- phase 1: global loads + smem stores (overlaps siblings' scans) ---
    {   // top halo
        float v = 0.f;
        if (y0 > 0) {
            int o = (y0 - 1) * Sn + x;
            v = __ldg(pb + o) * __ldg(ob + o);
        }
        s_img[0][x + 1] = v;
    }
    #pragma unroll
    for (int rr = 1; rr <= Rr; rr++) {      // always in-range
        int o = (y0 + rr - 1) * Sn + x;
        float pval = __ldg(pb + o);
        s_pred[rr - 1][x] = pval;
        s_img[rr][x + 1] = pval * __ldg(ob + o);
    }
    {   // bottom halo
        float v = 0.f;
        if (y0 + Rr < Sn) {
            int o = (y0 + Rr) * Sn + x;
            v = __ldg(pb + o) * __ldg(ob + o);
        }
        s_img[Rr + 1][x + 1] = v;
    }

    // --- spin until all 64 blocks of this batch finished scanning ---
    if (x == 0) {
        while (atomicAdd(&g_scan_done[b], 0) < TILES) { __nanosleep(32); }
        __threadfence();             // acquire
    }
    __syncthreads();                 // also orders phase-1 smem for sobel

    // point coords into registers (lane<16), broadcast via shfl
    int cload = 0;
    float pxv = FAR_COORD, pyv = FAR_COORD;
    if (lane == 0) cload = g_cnt[b];
    const int cnt = min(__shfl_sync(0xffffffffu, cload, 0), Kn);
    if (lane < Kn) {
        if (lane < cnt) { pxv = g_px[b][lane]; pyv = g_py[b][lane]; }
    }

    const float fx  = (float)x;
    const float fy0 = (float)y0;

    // --- phase 2a: exact per-warp point culling over the warp's 32xRr tile ---
    unsigned keep;
    {
        const float x0f = (float)(x & ~31);
        const float x1f = x0f + 31.0f;
        const float y1f = fy0 + (float)(Rr - 1);
        float lb = 3.0e38f, ubi = 3.0e38f;
        if (lane < Kn) {
            float dxl = x0f - pxv, dxr = pxv - x1f;
            float dxm = fmaxf(0.f, fmaxf(dxl, dxr));
            float dxM = fmaxf(fabsf(dxl), fabsf(x1f - pxv));
            float dyl = fy0 - pyv, dyr = pyv - y1f;
            float dym = fmaxf(0.f, fmaxf(dyl, dyr));
            float dyM = fmaxf(fabsf(dyl), fabsf(y1f - pyv));
            lb  = fmaf(dxm, dxm, dym * dym);
            ubi = fmaf(dxM, dxM, dyM * dyM);
        }
        float ub = ubi;
        #pragma unroll
        for (int o = 16; o > 0; o >>= 1)
            ub = fminf(ub, __shfl_xor_sync(0xffffffffu, ub, o));
        keep = __ballot_sync(0xffffffffu, lb <= ub);
    }

    // --- phase 2b: distance mins over surviving points (shfl-broadcast) ---
    float m[Rr];
    #pragma unroll
    for (int r = 0; r < Rr; r++) m[r] = 3.0e38f;

    unsigned mask = keep;
    while (mask) {
        int i = __ffs(mask) - 1;
        mask &= mask - 1;
        float px_i = __shfl_sync(0xffffffffu, pxv, i);
        float py_i = __shfl_sync(0xffffffffu, pyv, i);
        float dxv = fx - px_i;
        float dy0 = fy0 - py_i;
        float c = fmaf(dy0, dy0, dxv * dxv);
        float e = dy0 + dy0;
        #pragma unroll
        for (int r = 0; r < Rr; r++)
            m[r] = fminf(m[r], fmaf((float)r, e, c));       // d2(r) = m + r^2 later
    }

    float vsum = 0.f, vmax = 0.f;
    #pragma unroll
    for (int r = 0; r < Rr; r++) {
        float d2 = m[r] + (float)(r * r);
        float dist = (cnt > 0) ? sqrtf(d2) : EMPTY_DIST;
        float dd = fmaxf(dist - 1.0f, 0.f);
        vsum += s_pred[r][x] * dd;
        vmax = fmaxf(vmax, dd);
    }

    // --- phase 3: branch-free rolling-window sobel (masked accumulate) ---
    float gsum = 0.f;
    const float xokf = (x >= 1 && x <= Sn - 2) ? 1.f : 0.f;

    float a0l = s_img[0][x], a0c = s_img[0][x + 1], a0r = s_img[0][x + 2];
    float a1l = s_img[1][x],                        a1r = s_img[1][x + 2];

    #pragma unroll
    for (int r = 0; r < Rr; r++) {
        const int y = y0 + r;
        float a2l = s_img[r + 2][x], a2c = s_img[r + 2][x + 1], a2r = s_img[r + 2][x + 2];

        float t = a0c - a2c;     // n01 - n21
        float u = a1r - a1l;     // n12 - n10
        float p = a0r - a2l;     // n02 - n20
        float q = a0l - a2r;     // n00 - n22
        float g0 = fmaf(2.f, u, p - q);
        float g1 = fmaf(2.f, t, p + q);
        float g2 = fmaf(2.f, q, t - u);
        float g3 = fmaf(2.f, p, t + u);
        float gm = fmaxf(fmaxf(fabsf(g0), fabsf(g1)), fmaxf(fabsf(g2), fabsf(g3)));
        float maskf = (y >= 1 && y <= Sn - 2) ? xokf : 0.f;  // y part block-uniform
        gsum = fmaf(maskf, gm, gsum);

        a0l = a1l; a0c = s_img[r + 1][x + 1]; a0r = a1r;
        a1l = a2l;                            a1r = a2r;
    }

    // --- block reduction: sum(vsum), sum(gsum), max(vmax) ---
    #pragma unroll
    for (int o = 16; o > 0; o >>= 1) {
        vsum += __shfl_down_sync(0xffffffffu, vsum, o);
        gsum += __shfl_down_sync(0xffffffffu, gsum, o);
        vmax = fmaxf(vmax, __shfl_down_sync(0xffffffffu, vmax, o));
    }
    const int wid = x >> 5;
    if (lane == 0) { sh_s[wid] = vsum; sh_g[wid] = gsum; sh_m[wid] = vmax; }
    __syncthreads();
    if (wid == 0) {
        vsum = (lane < 16) ? sh_s[lane] : 0.f;
        gsum = (lane < 16) ? sh_g[lane] : 0.f;
        vmax = (lane < 16) ? sh_m[lane] : 0.f;
        #pragma unroll
        for (int o = 8; o > 0; o >>= 1) {
            vsum += __shfl_down_sync(0xffffffffu, vsum, o);
            gsum += __shfl_down_sync(0xffffffffu, gsum, o);
            vmax = fmaxf(vmax, __shfl_down_sync(0xffffffffu, vmax, o));
        }
        if (lane == 0) {
            atomicAdd(&g_numer[b], (double)vsum);
            atomicAdd(&g_gradsum, (double)gsum);
            atomicMax(&g_maxbits[b], __float_as_uint(vmax));

            __threadfence();
            unsigned ticket = atomicAdd(&g_done, 1u);
            const unsigned total = TILES * Bn;
            if (ticket == total - 1u) {
                double acc = 0.0;
                #pragma unroll
                for (int bb = 0; bb < Bn; bb++) {
                    float mx = __uint_as_float(g_maxbits[bb]);
                    acc += g_numer[bb] / (double)mx;
                    g_numer[bb] = 0.0;
                    g_maxbits[bb] = 0u;
                    g_cnt[bb] = 0;
                    g_scan_done[bb] = 0;
                }
                const double denom = (double)Sn * (double)Sn * (double)Bn;
                out[0] = (float)(acc / denom);
                out[1] = (float)(g_gradsum / denom);
                g_gradsum = 0.0;
                g_done = 0u;
                __threadfence();
            }
        }
    }
}

extern "C" void kernel_launch(void* const* d_in, const int* in_sizes, int n_in,
                              void* d_out, int out_size) {
    const float* pred = (const float*)d_in[0];
    const float* ptl  = (const float*)d_in[1];
    const float* ori  = (const float*)d_in[2];
    float* out = (float*)d_out;

    void* args[] = { (void*)&pred, (void*)&ori, (void*)&ptl, (void*)&out };
    cudaLaunchCooperativeKernel((void*)fused_kernel,
                                dim3(TILES, Bn), dim3(512),
                                args, 0, (cudaStream_t)0);
}